// round 6
// baseline (speedup 1.0000x reference)
#include <cuda_runtime.h>
#include <cuda_bf16.h>

// Problem constants (match reference_code)
#define NN 262144
#define KK 1024
#define DD 256
#define NBLK 128              // fused-prologue CTAs (all co-resident)
#define CHUNK 2048            // indices per CTA (NN / NBLK)
#define DECAY 0.99f
#define ONE_MINUS_DECAY 0.01f
#define EPS 1e-5f

// Scratch (device globals; no allocation allowed)
__device__ int      g_bh[NBLK * KK];     // [b][k] hist -> exclusive prefix over b
__device__ int      g_ktotal[KK];        // per-code total count
__device__ int      g_offsets[KK + 1];   // exclusive scan over codes
__device__ int      g_order[NN];         // row ids grouped by code
__device__ float    g_inv_smoothed[KK];
__device__ unsigned g_bar_cnt[4];        // software grid barrier state
__device__ unsigned g_bar_gen[4];        // (zero-init; replay-safe: gen monotone)

// ---------------------------------------------------------------------------
// Software grid barrier (all NBLK CTAs co-resident by construction).
// ---------------------------------------------------------------------------
__device__ __forceinline__ void grid_barrier(int id) {
    __syncthreads();
    if (threadIdx.x == 0) {
        volatile unsigned* genp = &g_bar_gen[id];
        unsigned gen = *genp;
        __threadfence();
        unsigned arrived = atomicAdd(&g_bar_cnt[id], 1u);
        if (arrived == (unsigned)(NBLK - 1)) {
            g_bar_cnt[id] = 0u;
            __threadfence();
            *genp = gen + 1u;
        } else {
            while (*genp == gen) { __nanosleep(64); }
        }
        __threadfence();
    }
    __syncthreads();
}

// ---------------------------------------------------------------------------
// Fused prologue: hist -> transpose scan -> code scan/cs epilogue -> scatter.
// Indices are read ONCE into registers and reused for the scatter phase.
// ---------------------------------------------------------------------------
__global__ void __launch_bounds__(1024) k_prologue(
    const int* __restrict__ idx,
    const float* __restrict__ cluster_size,
    float* __restrict__ out_cs) {
    __shared__ union {
        int h[KK];            // phase A: histogram / phase D: cursors
        int s[NBLK][33];      // phase B: transpose-scan tile (padded)
        struct { int wsum[32]; float wred[32]; float n_sh; } cs;  // phase C
    } sm;

    int t = threadIdx.x;
    int b = blockIdx.x;
    int lane = t & 31, warp = t >> 5;

    // ---- Phase A: per-CTA histogram (indices -> registers) ----
    sm.h[t] = 0;
    __syncthreads();
    int base = b * CHUNK;
    int k0 = idx[base + t];
    int k1 = idx[base + 1024 + t];
    atomicAdd(&sm.h[k0], 1);
    atomicAdd(&sm.h[k1], 1);
    __syncthreads();
    g_bh[b * KK + t] = sm.h[t];               // contiguous 4KB per CTA

    grid_barrier(0);

    // ---- Phase B: CTAs 0..31 transpose-scan g_bh along b for 32 codes each ----
    if (b < 32) {
        int c0 = b * 32;
        #pragma unroll
        for (int r = 0; r < 4; ++r) {
            int row = r * 32 + warp;
            sm.s[row][lane] = g_bh[row * KK + c0 + lane];
        }
        __syncthreads();
        {
            int w = warp;
            int carry = 0;
            #pragma unroll
            for (int seg = 0; seg < 4; ++seg) {
                int v = sm.s[seg * 32 + lane][w];
                int incl = v;
                #pragma unroll
                for (int o = 1; o < 32; o <<= 1) {
                    int x = __shfl_up_sync(0xffffffffu, incl, o);
                    if (lane >= o) incl += x;
                }
                sm.s[seg * 32 + lane][w] = carry + incl - v;   // exclusive
                carry += __shfl_sync(0xffffffffu, incl, 31);
            }
            if (lane == 0) g_ktotal[c0 + w] = carry;
        }
        __syncthreads();
        #pragma unroll
        for (int r = 0; r < 4; ++r) {
            int row = r * 32 + warp;
            g_bh[row * KK + c0 + lane] = sm.s[row][lane];
        }
    }

    grid_barrier(1);

    // ---- Phase C: CTA 32 scans code totals + cs epilogue ----
    if (b == 32) {
        int c = g_ktotal[t];
        int incl = c;
        #pragma unroll
        for (int o = 1; o < 32; o <<= 1) {
            int x = __shfl_up_sync(0xffffffffu, incl, o);
            if (lane >= o) incl += x;
        }
        if (lane == 31) sm.cs.wsum[warp] = incl;
        __syncthreads();
        if (warp == 0) {
            int s = sm.cs.wsum[lane];
            int si = s;
            #pragma unroll
            for (int o = 1; o < 32; o <<= 1) {
                int x = __shfl_up_sync(0xffffffffu, si, o);
                if (lane >= o) si += x;
            }
            sm.cs.wsum[lane] = si - s;
        }
        __syncthreads();
        int excl = incl - c + sm.cs.wsum[warp];

        g_offsets[t] = excl;
        if (t == KK - 1) g_offsets[KK] = excl + c;

        float ncs = cluster_size[t] * DECAY + ONE_MINUS_DECAY * (float)c;
        out_cs[t] = ncs;

        float v = ncs;
        #pragma unroll
        for (int o = 16; o > 0; o >>= 1)
            v += __shfl_down_sync(0xffffffffu, v, o);
        if (lane == 0) sm.cs.wred[warp] = v;
        __syncthreads();
        if (warp == 0) {
            float s = sm.cs.wred[lane];
            #pragma unroll
            for (int o = 16; o > 0; o >>= 1)
                s += __shfl_down_sync(0xffffffffu, s, o);
            if (lane == 0) sm.cs.n_sh = s;
        }
        __syncthreads();
        float n = sm.cs.n_sh;

        float smoothed = (ncs + EPS) / (n + (float)KK * EPS) * n;
        g_inv_smoothed[t] = 1.0f / smoothed;
    }

    grid_barrier(2);

    // ---- Phase D: scatter with register-held indices ----
    sm.h[t] = g_offsets[t] + g_bh[b * KK + t];   // coalesced, L2-hot
    __syncthreads();
    int p0 = atomicAdd(&sm.h[k0], 1);
    g_order[p0] = base + t;
    int p1 = atomicAdd(&sm.h[k1], 1);
    g_order[p1] = base + 1024 + t;
}

// ---------------------------------------------------------------------------
// Reduce: per-code gather-reduce (float4) + fused EMA epilogue.
// 128-thread blocks (2 row-phases x 64 float4 lanes) so that all 1024 CTAs
// are co-resident in ONE wave (7 CTAs/SM) -> no wave-quantization tail.
// g_order staged through smem; enc loads are 4-deep independent streams.
// ---------------------------------------------------------------------------
__global__ void __launch_bounds__(128) k_reduce(
    const float4* __restrict__ enc,        // [N, 64] float4
    const float4* __restrict__ embed_avg,  // [K, 64] float4
    float4* __restrict__ out_ea,
    float4* __restrict__ out_norm) {
    __shared__ int ord[1024];
    __shared__ float4 sh[64];

    int k = blockIdx.x;
    int d4 = threadIdx.x & 63;      // float4 column 0..63
    int ph = threadIdx.x >> 6;      // row phase 0..1

    int start = g_offsets[k];
    int cnt   = g_offsets[k + 1] - start;

    float4 a0 = make_float4(0.f, 0.f, 0.f, 0.f);
    float4 a1 = make_float4(0.f, 0.f, 0.f, 0.f);
    float4 a2 = make_float4(0.f, 0.f, 0.f, 0.f);
    float4 a3 = make_float4(0.f, 0.f, 0.f, 0.f);

    for (int t0 = 0; t0 < cnt; t0 += 1024) {
        int tile = min(1024, cnt - t0);
        __syncthreads();
        for (int i = threadIdx.x; i < tile; i += 128)
            ord[i] = g_order[start + t0 + i];
        __syncthreads();

        int j = ph;
        // 4 independent float4 loads in flight per thread
        for (; j + 6 < tile; j += 8) {
            int r0 = ord[j];
            int r1 = ord[j + 2];
            int r2 = ord[j + 4];
            int r3 = ord[j + 6];
            float4 v0 = __ldg(enc + (size_t)r0 * 64 + d4);
            float4 v1 = __ldg(enc + (size_t)r1 * 64 + d4);
            float4 v2 = __ldg(enc + (size_t)r2 * 64 + d4);
            float4 v3 = __ldg(enc + (size_t)r3 * 64 + d4);
            a0.x += v0.x; a0.y += v0.y; a0.z += v0.z; a0.w += v0.w;
            a1.x += v1.x; a1.y += v1.y; a1.z += v1.z; a1.w += v1.w;
            a2.x += v2.x; a2.y += v2.y; a2.z += v2.z; a2.w += v2.w;
            a3.x += v3.x; a3.y += v3.y; a3.z += v3.z; a3.w += v3.w;
        }
        for (; j < tile; j += 2) {
            int r = ord[j];
            float4 v = __ldg(enc + (size_t)r * 64 + d4);
            a0.x += v.x; a0.y += v.y; a0.z += v.z; a0.w += v.w;
        }
    }

    a0.x += a1.x + a2.x + a3.x;
    a0.y += a1.y + a2.y + a3.y;
    a0.z += a1.z + a2.z + a3.z;
    a0.w += a1.w + a2.w + a3.w;

    if (ph == 1) sh[d4] = a0;
    __syncthreads();

    if (ph == 0) {
        float4 s1 = sh[d4];
        float4 acc;
        acc.x = a0.x + s1.x;
        acc.y = a0.y + s1.y;
        acc.z = a0.z + s1.z;
        acc.w = a0.w + s1.w;

        size_t o = (size_t)k * 64 + d4;
        float4 ea = embed_avg[o];
        float4 nea;
        nea.x = ea.x * DECAY + ONE_MINUS_DECAY * acc.x;
        nea.y = ea.y * DECAY + ONE_MINUS_DECAY * acc.y;
        nea.z = ea.z * DECAY + ONE_MINUS_DECAY * acc.z;
        nea.w = ea.w * DECAY + ONE_MINUS_DECAY * acc.w;
        out_ea[o] = nea;
        float inv = g_inv_smoothed[k];
        float4 nrm;
        nrm.x = nea.x * inv; nrm.y = nea.y * inv;
        nrm.z = nea.z * inv; nrm.w = nea.w * inv;
        out_norm[o] = nrm;
    }
}

// ---------------------------------------------------------------------------
// Launch
// Inputs (metadata order): indices[int32 N], encodings[f32 N*D],
//                          cluster_size[f32 K], embed_avg[f32 K*D]
// Output: concat(new_cs[K], new_ea[K*D], embed_normalized[K*D])
// ---------------------------------------------------------------------------
extern "C" void kernel_launch(void* const* d_in, const int* in_sizes, int n_in,
                              void* d_out, int out_size) {
    const int*   indices      = (const int*)d_in[0];
    const float* encodings    = (const float*)d_in[1];
    const float* cluster_size = (const float*)d_in[2];
    const float* embed_avg    = (const float*)d_in[3];

    float* out_cs   = (float*)d_out;                 // [K]
    float* out_ea   = out_cs + KK;                   // [K, D]
    float* out_norm = out_ea + (size_t)KK * DD;      // [K, D]

    k_prologue<<<NBLK, 1024>>>(indices, cluster_size, out_cs);
    k_reduce<<<KK, 128>>>((const float4*)encodings, (const float4*)embed_avg,
                          (float4*)out_ea, (float4*)out_norm);
}

// round 7
// speedup vs baseline: 1.0438x; 1.0438x over previous
#include <cuda_runtime.h>
#include <cuda_bf16.h>

// Problem constants (match reference_code)
#define NN 262144
#define KK 1024
#define DD 256
#define NBLK 128              // fused-prologue CTAs (all co-resident)
#define CHUNK 2048            // indices per CTA (NN / NBLK)
#define DECAY 0.99f
#define ONE_MINUS_DECAY 0.01f
#define EPS 1e-5f

// Scratch (device globals; no allocation allowed)
__device__ int      g_bh[NBLK * KK];     // [b][k] hist -> exclusive prefix over b
__device__ int      g_ktotal[KK];        // per-code total count
__device__ int      g_offsets[KK + 1];   // exclusive scan over codes
__device__ int      g_order[NN];         // row ids grouped by code
__device__ float    g_inv_smoothed[KK];
__device__ unsigned g_bar_cnt[4];        // software grid barrier state
__device__ unsigned g_bar_gen[4];        // (zero-init; replay-safe: gen monotone)

// ---------------------------------------------------------------------------
// Software grid barrier (all NBLK CTAs co-resident by construction).
// ---------------------------------------------------------------------------
__device__ __forceinline__ void grid_barrier(int id) {
    __syncthreads();
    if (threadIdx.x == 0) {
        volatile unsigned* genp = &g_bar_gen[id];
        unsigned gen = *genp;
        __threadfence();
        unsigned arrived = atomicAdd(&g_bar_cnt[id], 1u);
        if (arrived == (unsigned)(NBLK - 1)) {
            g_bar_cnt[id] = 0u;
            __threadfence();
            *genp = gen + 1u;
        } else {
            while (*genp == gen) { __nanosleep(64); }
        }
        __threadfence();
    }
    __syncthreads();
}

// ---------------------------------------------------------------------------
// Fused prologue: hist -> transpose scan -> code scan/cs epilogue -> scatter.
// (unchanged from round 5/6 — validated at ~12.5us incl. launch)
// ---------------------------------------------------------------------------
__global__ void __launch_bounds__(1024) k_prologue(
    const int* __restrict__ idx,
    const float* __restrict__ cluster_size,
    float* __restrict__ out_cs) {
    __shared__ union {
        int h[KK];            // phase A: histogram / phase D: cursors
        int s[NBLK][33];      // phase B: transpose-scan tile (padded)
        struct { int wsum[32]; float wred[32]; float n_sh; } cs;  // phase C
    } sm;

    int t = threadIdx.x;
    int b = blockIdx.x;
    int lane = t & 31, warp = t >> 5;

    // ---- Phase A: per-CTA histogram (indices -> registers) ----
    sm.h[t] = 0;
    __syncthreads();
    int base = b * CHUNK;
    int k0 = idx[base + t];
    int k1 = idx[base + 1024 + t];
    atomicAdd(&sm.h[k0], 1);
    atomicAdd(&sm.h[k1], 1);
    __syncthreads();
    g_bh[b * KK + t] = sm.h[t];               // contiguous 4KB per CTA

    grid_barrier(0);

    // ---- Phase B: CTAs 0..31 transpose-scan g_bh along b for 32 codes each ----
    if (b < 32) {
        int c0 = b * 32;
        #pragma unroll
        for (int r = 0; r < 4; ++r) {
            int row = r * 32 + warp;
            sm.s[row][lane] = g_bh[row * KK + c0 + lane];
        }
        __syncthreads();
        {
            int w = warp;
            int carry = 0;
            #pragma unroll
            for (int seg = 0; seg < 4; ++seg) {
                int v = sm.s[seg * 32 + lane][w];
                int incl = v;
                #pragma unroll
                for (int o = 1; o < 32; o <<= 1) {
                    int x = __shfl_up_sync(0xffffffffu, incl, o);
                    if (lane >= o) incl += x;
                }
                sm.s[seg * 32 + lane][w] = carry + incl - v;   // exclusive
                carry += __shfl_sync(0xffffffffu, incl, 31);
            }
            if (lane == 0) g_ktotal[c0 + w] = carry;
        }
        __syncthreads();
        #pragma unroll
        for (int r = 0; r < 4; ++r) {
            int row = r * 32 + warp;
            g_bh[row * KK + c0 + lane] = sm.s[row][lane];
        }
    }

    grid_barrier(1);

    // ---- Phase C: CTA 32 scans code totals + cs epilogue ----
    if (b == 32) {
        int c = g_ktotal[t];
        int incl = c;
        #pragma unroll
        for (int o = 1; o < 32; o <<= 1) {
            int x = __shfl_up_sync(0xffffffffu, incl, o);
            if (lane >= o) incl += x;
        }
        if (lane == 31) sm.cs.wsum[warp] = incl;
        __syncthreads();
        if (warp == 0) {
            int s = sm.cs.wsum[lane];
            int si = s;
            #pragma unroll
            for (int o = 1; o < 32; o <<= 1) {
                int x = __shfl_up_sync(0xffffffffu, si, o);
                if (lane >= o) si += x;
            }
            sm.cs.wsum[lane] = si - s;
        }
        __syncthreads();
        int excl = incl - c + sm.cs.wsum[warp];

        g_offsets[t] = excl;
        if (t == KK - 1) g_offsets[KK] = excl + c;

        float ncs = cluster_size[t] * DECAY + ONE_MINUS_DECAY * (float)c;
        out_cs[t] = ncs;

        float v = ncs;
        #pragma unroll
        for (int o = 16; o > 0; o >>= 1)
            v += __shfl_down_sync(0xffffffffu, v, o);
        if (lane == 0) sm.cs.wred[warp] = v;
        __syncthreads();
        if (warp == 0) {
            float s = sm.cs.wred[lane];
            #pragma unroll
            for (int o = 16; o > 0; o >>= 1)
                s += __shfl_down_sync(0xffffffffu, s, o);
            if (lane == 0) sm.cs.n_sh = s;
        }
        __syncthreads();
        float n = sm.cs.n_sh;

        float smoothed = (ncs + EPS) / (n + (float)KK * EPS) * n;
        g_inv_smoothed[t] = 1.0f / smoothed;
    }

    grid_barrier(2);

    // ---- Phase D: scatter with register-held indices ----
    sm.h[t] = g_offsets[t] + g_bh[b * KK + t];   // coalesced, L2-hot
    __syncthreads();
    int p0 = atomicAdd(&sm.h[k0], 1);
    g_order[p0] = base + t;
    int p1 = atomicAdd(&sm.h[k1], 1);
    g_order[p1] = base + 1024 + t;
}

// ---------------------------------------------------------------------------
// Reduce: per-code gather-reduce + fused EMA epilogue.
// 128 threads (64 float4 lanes x 2 row-phases), 1024 CTAs single wave
// (>=7 CTAs/SM), and 8 INDEPENDENT float4 load streams per thread so
// in-flight bytes (~113KB/SM) comfortably exceed the loaded latency-BW
// product. g_order staged through smem.
// ---------------------------------------------------------------------------
__global__ void __launch_bounds__(128) k_reduce(
    const float4* __restrict__ enc,        // [N, 64] float4
    const float4* __restrict__ embed_avg,  // [K, 64] float4
    float4* __restrict__ out_ea,
    float4* __restrict__ out_norm) {
    __shared__ int ord[1024];
    __shared__ float4 sh[64];

    int k = blockIdx.x;
    int d4 = threadIdx.x & 63;      // float4 column 0..63
    int ph = threadIdx.x >> 6;      // row phase 0..1

    int start = g_offsets[k];
    int cnt   = g_offsets[k + 1] - start;

    float4 a0 = make_float4(0.f, 0.f, 0.f, 0.f);
    float4 a1 = make_float4(0.f, 0.f, 0.f, 0.f);
    float4 a2 = make_float4(0.f, 0.f, 0.f, 0.f);
    float4 a3 = make_float4(0.f, 0.f, 0.f, 0.f);
    float4 a4 = make_float4(0.f, 0.f, 0.f, 0.f);
    float4 a5 = make_float4(0.f, 0.f, 0.f, 0.f);
    float4 a6 = make_float4(0.f, 0.f, 0.f, 0.f);
    float4 a7 = make_float4(0.f, 0.f, 0.f, 0.f);

    for (int t0 = 0; t0 < cnt; t0 += 1024) {
        int tile = min(1024, cnt - t0);
        __syncthreads();
        for (int i = threadIdx.x; i < tile; i += 128)
            ord[i] = g_order[start + t0 + i];
        __syncthreads();

        int j = ph;
        // 8 independent float4 loads in flight per thread
        for (; j + 14 < tile; j += 16) {
            int r0 = ord[j];
            int r1 = ord[j + 2];
            int r2 = ord[j + 4];
            int r3 = ord[j + 6];
            int r4 = ord[j + 8];
            int r5 = ord[j + 10];
            int r6 = ord[j + 12];
            int r7 = ord[j + 14];
            float4 v0 = __ldg(enc + (size_t)r0 * 64 + d4);
            float4 v1 = __ldg(enc + (size_t)r1 * 64 + d4);
            float4 v2 = __ldg(enc + (size_t)r2 * 64 + d4);
            float4 v3 = __ldg(enc + (size_t)r3 * 64 + d4);
            float4 v4 = __ldg(enc + (size_t)r4 * 64 + d4);
            float4 v5 = __ldg(enc + (size_t)r5 * 64 + d4);
            float4 v6 = __ldg(enc + (size_t)r6 * 64 + d4);
            float4 v7 = __ldg(enc + (size_t)r7 * 64 + d4);
            a0.x += v0.x; a0.y += v0.y; a0.z += v0.z; a0.w += v0.w;
            a1.x += v1.x; a1.y += v1.y; a1.z += v1.z; a1.w += v1.w;
            a2.x += v2.x; a2.y += v2.y; a2.z += v2.z; a2.w += v2.w;
            a3.x += v3.x; a3.y += v3.y; a3.z += v3.z; a3.w += v3.w;
            a4.x += v4.x; a4.y += v4.y; a4.z += v4.z; a4.w += v4.w;
            a5.x += v5.x; a5.y += v5.y; a5.z += v5.z; a5.w += v5.w;
            a6.x += v6.x; a6.y += v6.y; a6.z += v6.z; a6.w += v6.w;
            a7.x += v7.x; a7.y += v7.y; a7.z += v7.z; a7.w += v7.w;
        }
        for (; j < tile; j += 2) {
            int r = ord[j];
            float4 v = __ldg(enc + (size_t)r * 64 + d4);
            a0.x += v.x; a0.y += v.y; a0.z += v.z; a0.w += v.w;
        }
    }

    a0.x = ((a0.x + a1.x) + (a2.x + a3.x)) + ((a4.x + a5.x) + (a6.x + a7.x));
    a0.y = ((a0.y + a1.y) + (a2.y + a3.y)) + ((a4.y + a5.y) + (a6.y + a7.y));
    a0.z = ((a0.z + a1.z) + (a2.z + a3.z)) + ((a4.z + a5.z) + (a6.z + a7.z));
    a0.w = ((a0.w + a1.w) + (a2.w + a3.w)) + ((a4.w + a5.w) + (a6.w + a7.w));

    __syncthreads();
    if (ph == 1) sh[d4] = a0;
    __syncthreads();

    if (ph == 0) {
        float4 s1 = sh[d4];
        float4 acc;
        acc.x = a0.x + s1.x;
        acc.y = a0.y + s1.y;
        acc.z = a0.z + s1.z;
        acc.w = a0.w + s1.w;

        size_t o = (size_t)k * 64 + d4;
        float4 ea = embed_avg[o];
        float4 nea;
        nea.x = ea.x * DECAY + ONE_MINUS_DECAY * acc.x;
        nea.y = ea.y * DECAY + ONE_MINUS_DECAY * acc.y;
        nea.z = ea.z * DECAY + ONE_MINUS_DECAY * acc.z;
        nea.w = ea.w * DECAY + ONE_MINUS_DECAY * acc.w;
        out_ea[o] = nea;
        float inv = g_inv_smoothed[k];
        float4 nrm;
        nrm.x = nea.x * inv; nrm.y = nea.y * inv;
        nrm.z = nea.z * inv; nrm.w = nea.w * inv;
        out_norm[o] = nrm;
    }
}

// ---------------------------------------------------------------------------
// Launch
// Inputs (metadata order): indices[int32 N], encodings[f32 N*D],
//                          cluster_size[f32 K], embed_avg[f32 K*D]
// Output: concat(new_cs[K], new_ea[K*D], embed_normalized[K*D])
// ---------------------------------------------------------------------------
extern "C" void kernel_launch(void* const* d_in, const int* in_sizes, int n_in,
                              void* d_out, int out_size) {
    const int*   indices      = (const int*)d_in[0];
    const float* encodings    = (const float*)d_in[1];
    const float* cluster_size = (const float*)d_in[2];
    const float* embed_avg    = (const float*)d_in[3];

    float* out_cs   = (float*)d_out;                 // [K]
    float* out_ea   = out_cs + KK;                   // [K, D]
    float* out_norm = out_ea + (size_t)KK * DD;      // [K, D]

    k_prologue<<<NBLK, 1024>>>(indices, cluster_size, out_cs);
    k_reduce<<<KK, 128>>>((const float4*)encodings, (const float4*)embed_avg,
                          (float4*)out_ea, (float4*)out_norm);
}

// round 8
// speedup vs baseline: 1.0697x; 1.0248x over previous
#include <cuda_runtime.h>
#include <cuda_bf16.h>

// Problem constants (match reference_code)
#define NN 262144
#define KK 1024
#define DD 256
#define NBLK 128              // fused-prologue CTAs (all co-resident)
#define CHUNK 2048            // indices per CTA (NN / NBLK)
#define DECAY 0.99f
#define ONE_MINUS_DECAY 0.01f
#define EPS 1e-5f

// Scratch (device globals; no allocation allowed)
__device__ int      g_bh[NBLK * KK];     // [b][k] hist -> exclusive prefix over b
__device__ int      g_ktotal[KK];        // per-code total count
__device__ int      g_offsets[KK + 1];   // exclusive scan over codes
__device__ int      g_order[NN];         // row ids grouped by code
__device__ float    g_inv_smoothed[KK];
__device__ unsigned g_bar_cnt[4];        // software grid barrier state
__device__ unsigned g_bar_gen[4];        // (zero-init; replay-safe: gen monotone)

// ---------------------------------------------------------------------------
// Software grid barrier (all NBLK CTAs co-resident by construction).
// ---------------------------------------------------------------------------
__device__ __forceinline__ void grid_barrier(int id) {
    __syncthreads();
    if (threadIdx.x == 0) {
        volatile unsigned* genp = &g_bar_gen[id];
        unsigned gen = *genp;
        __threadfence();
        unsigned arrived = atomicAdd(&g_bar_cnt[id], 1u);
        if (arrived == (unsigned)(NBLK - 1)) {
            g_bar_cnt[id] = 0u;
            __threadfence();
            *genp = gen + 1u;
        } else {
            while (*genp == gen) { __nanosleep(64); }
        }
        __threadfence();
    }
    __syncthreads();
}

// ---------------------------------------------------------------------------
// Fused prologue: hist -> transpose scan -> code scan/cs epilogue -> scatter.
// (unchanged from round 5/6 — validated at ~12.5us incl. launch)
// ---------------------------------------------------------------------------
__global__ void __launch_bounds__(1024) k_prologue(
    const int* __restrict__ idx,
    const float* __restrict__ cluster_size,
    float* __restrict__ out_cs) {
    __shared__ union {
        int h[KK];            // phase A: histogram / phase D: cursors
        int s[NBLK][33];      // phase B: transpose-scan tile (padded)
        struct { int wsum[32]; float wred[32]; float n_sh; } cs;  // phase C
    } sm;

    int t = threadIdx.x;
    int b = blockIdx.x;
    int lane = t & 31, warp = t >> 5;

    // ---- Phase A: per-CTA histogram (indices -> registers) ----
    sm.h[t] = 0;
    __syncthreads();
    int base = b * CHUNK;
    int k0 = idx[base + t];
    int k1 = idx[base + 1024 + t];
    atomicAdd(&sm.h[k0], 1);
    atomicAdd(&sm.h[k1], 1);
    __syncthreads();
    g_bh[b * KK + t] = sm.h[t];               // contiguous 4KB per CTA

    grid_barrier(0);

    // ---- Phase B: CTAs 0..31 transpose-scan g_bh along b for 32 codes each ----
    if (b < 32) {
        int c0 = b * 32;
        #pragma unroll
        for (int r = 0; r < 4; ++r) {
            int row = r * 32 + warp;
            sm.s[row][lane] = g_bh[row * KK + c0 + lane];
        }
        __syncthreads();
        {
            int w = warp;
            int carry = 0;
            #pragma unroll
            for (int seg = 0; seg < 4; ++seg) {
                int v = sm.s[seg * 32 + lane][w];
                int incl = v;
                #pragma unroll
                for (int o = 1; o < 32; o <<= 1) {
                    int x = __shfl_up_sync(0xffffffffu, incl, o);
                    if (lane >= o) incl += x;
                }
                sm.s[seg * 32 + lane][w] = carry + incl - v;   // exclusive
                carry += __shfl_sync(0xffffffffu, incl, 31);
            }
            if (lane == 0) g_ktotal[c0 + w] = carry;
        }
        __syncthreads();
        #pragma unroll
        for (int r = 0; r < 4; ++r) {
            int row = r * 32 + warp;
            g_bh[row * KK + c0 + lane] = sm.s[row][lane];
        }
    }

    grid_barrier(1);

    // ---- Phase C: CTA 32 scans code totals + cs epilogue ----
    if (b == 32) {
        int c = g_ktotal[t];
        int incl = c;
        #pragma unroll
        for (int o = 1; o < 32; o <<= 1) {
            int x = __shfl_up_sync(0xffffffffu, incl, o);
            if (lane >= o) incl += x;
        }
        if (lane == 31) sm.cs.wsum[warp] = incl;
        __syncthreads();
        if (warp == 0) {
            int s = sm.cs.wsum[lane];
            int si = s;
            #pragma unroll
            for (int o = 1; o < 32; o <<= 1) {
                int x = __shfl_up_sync(0xffffffffu, si, o);
                if (lane >= o) si += x;
            }
            sm.cs.wsum[lane] = si - s;
        }
        __syncthreads();
        int excl = incl - c + sm.cs.wsum[warp];

        g_offsets[t] = excl;
        if (t == KK - 1) g_offsets[KK] = excl + c;

        float ncs = cluster_size[t] * DECAY + ONE_MINUS_DECAY * (float)c;
        out_cs[t] = ncs;

        float v = ncs;
        #pragma unroll
        for (int o = 16; o > 0; o >>= 1)
            v += __shfl_down_sync(0xffffffffu, v, o);
        if (lane == 0) sm.cs.wred[warp] = v;
        __syncthreads();
        if (warp == 0) {
            float s = sm.cs.wred[lane];
            #pragma unroll
            for (int o = 16; o > 0; o >>= 1)
                s += __shfl_down_sync(0xffffffffu, s, o);
            if (lane == 0) sm.cs.n_sh = s;
        }
        __syncthreads();
        float n = sm.cs.n_sh;

        float smoothed = (ncs + EPS) / (n + (float)KK * EPS) * n;
        g_inv_smoothed[t] = 1.0f / smoothed;
    }

    grid_barrier(2);

    // ---- Phase D: scatter with register-held indices ----
    sm.h[t] = g_offsets[t] + g_bh[b * KK + t];   // coalesced, L2-hot
    __syncthreads();
    int p0 = atomicAdd(&sm.h[k0], 1);
    g_order[p0] = base + t;
    int p1 = atomicAdd(&sm.h[k1], 1);
    g_order[p1] = base + 1024 + t;
}

// ---------------------------------------------------------------------------
// Reduce: per-code gather-reduce + fused EMA epilogue.
// 128 threads (64 float4 lanes x 2 row-phases), 1024 CTAs single wave
// (>=7 CTAs/SM), and 8 INDEPENDENT float4 load streams per thread so
// in-flight bytes (~113KB/SM) comfortably exceed the loaded latency-BW
// product. g_order staged through smem.
// ---------------------------------------------------------------------------
__global__ void __launch_bounds__(128) k_reduce(
    const float4* __restrict__ enc,        // [N, 64] float4
    const float4* __restrict__ embed_avg,  // [K, 64] float4
    float4* __restrict__ out_ea,
    float4* __restrict__ out_norm) {
    __shared__ int ord[1024];
    __shared__ float4 sh[64];

    int k = blockIdx.x;
    int d4 = threadIdx.x & 63;      // float4 column 0..63
    int ph = threadIdx.x >> 6;      // row phase 0..1

    int start = g_offsets[k];
    int cnt   = g_offsets[k + 1] - start;

    float4 a0 = make_float4(0.f, 0.f, 0.f, 0.f);
    float4 a1 = make_float4(0.f, 0.f, 0.f, 0.f);
    float4 a2 = make_float4(0.f, 0.f, 0.f, 0.f);
    float4 a3 = make_float4(0.f, 0.f, 0.f, 0.f);
    float4 a4 = make_float4(0.f, 0.f, 0.f, 0.f);
    float4 a5 = make_float4(0.f, 0.f, 0.f, 0.f);
    float4 a6 = make_float4(0.f, 0.f, 0.f, 0.f);
    float4 a7 = make_float4(0.f, 0.f, 0.f, 0.f);

    for (int t0 = 0; t0 < cnt; t0 += 1024) {
        int tile = min(1024, cnt - t0);
        __syncthreads();
        for (int i = threadIdx.x; i < tile; i += 128)
            ord[i] = g_order[start + t0 + i];
        __syncthreads();

        int j = ph;
        // 8 independent float4 loads in flight per thread
        for (; j + 14 < tile; j += 16) {
            int r0 = ord[j];
            int r1 = ord[j + 2];
            int r2 = ord[j + 4];
            int r3 = ord[j + 6];
            int r4 = ord[j + 8];
            int r5 = ord[j + 10];
            int r6 = ord[j + 12];
            int r7 = ord[j + 14];
            float4 v0 = __ldg(enc + (size_t)r0 * 64 + d4);
            float4 v1 = __ldg(enc + (size_t)r1 * 64 + d4);
            float4 v2 = __ldg(enc + (size_t)r2 * 64 + d4);
            float4 v3 = __ldg(enc + (size_t)r3 * 64 + d4);
            float4 v4 = __ldg(enc + (size_t)r4 * 64 + d4);
            float4 v5 = __ldg(enc + (size_t)r5 * 64 + d4);
            float4 v6 = __ldg(enc + (size_t)r6 * 64 + d4);
            float4 v7 = __ldg(enc + (size_t)r7 * 64 + d4);
            a0.x += v0.x; a0.y += v0.y; a0.z += v0.z; a0.w += v0.w;
            a1.x += v1.x; a1.y += v1.y; a1.z += v1.z; a1.w += v1.w;
            a2.x += v2.x; a2.y += v2.y; a2.z += v2.z; a2.w += v2.w;
            a3.x += v3.x; a3.y += v3.y; a3.z += v3.z; a3.w += v3.w;
            a4.x += v4.x; a4.y += v4.y; a4.z += v4.z; a4.w += v4.w;
            a5.x += v5.x; a5.y += v5.y; a5.z += v5.z; a5.w += v5.w;
            a6.x += v6.x; a6.y += v6.y; a6.z += v6.z; a6.w += v6.w;
            a7.x += v7.x; a7.y += v7.y; a7.z += v7.z; a7.w += v7.w;
        }
        for (; j < tile; j += 2) {
            int r = ord[j];
            float4 v = __ldg(enc + (size_t)r * 64 + d4);
            a0.x += v.x; a0.y += v.y; a0.z += v.z; a0.w += v.w;
        }
    }

    a0.x = ((a0.x + a1.x) + (a2.x + a3.x)) + ((a4.x + a5.x) + (a6.x + a7.x));
    a0.y = ((a0.y + a1.y) + (a2.y + a3.y)) + ((a4.y + a5.y) + (a6.y + a7.y));
    a0.z = ((a0.z + a1.z) + (a2.z + a3.z)) + ((a4.z + a5.z) + (a6.z + a7.z));
    a0.w = ((a0.w + a1.w) + (a2.w + a3.w)) + ((a4.w + a5.w) + (a6.w + a7.w));

    __syncthreads();
    if (ph == 1) sh[d4] = a0;
    __syncthreads();

    if (ph == 0) {
        float4 s1 = sh[d4];
        float4 acc;
        acc.x = a0.x + s1.x;
        acc.y = a0.y + s1.y;
        acc.z = a0.z + s1.z;
        acc.w = a0.w + s1.w;

        size_t o = (size_t)k * 64 + d4;
        float4 ea = embed_avg[o];
        float4 nea;
        nea.x = ea.x * DECAY + ONE_MINUS_DECAY * acc.x;
        nea.y = ea.y * DECAY + ONE_MINUS_DECAY * acc.y;
        nea.z = ea.z * DECAY + ONE_MINUS_DECAY * acc.z;
        nea.w = ea.w * DECAY + ONE_MINUS_DECAY * acc.w;
        out_ea[o] = nea;
        float inv = g_inv_smoothed[k];
        float4 nrm;
        nrm.x = nea.x * inv; nrm.y = nea.y * inv;
        nrm.z = nea.z * inv; nrm.w = nea.w * inv;
        out_norm[o] = nrm;
    }
}

// ---------------------------------------------------------------------------
// Launch
// Inputs (metadata order): indices[int32 N], encodings[f32 N*D],
//                          cluster_size[f32 K], embed_avg[f32 K*D]
// Output: concat(new_cs[K], new_ea[K*D], embed_normalized[K*D])
// ---------------------------------------------------------------------------
extern "C" void kernel_launch(void* const* d_in, const int* in_sizes, int n_in,
                              void* d_out, int out_size) {
    const int*   indices      = (const int*)d_in[0];
    const float* encodings    = (const float*)d_in[1];
    const float* cluster_size = (const float*)d_in[2];
    const float* embed_avg    = (const float*)d_in[3];

    float* out_cs   = (float*)d_out;                 // [K]
    float* out_ea   = out_cs + KK;                   // [K, D]
    float* out_norm = out_ea + (size_t)KK * DD;      // [K, D]

    k_prologue<<<NBLK, 1024>>>(indices, cluster_size, out_cs);
    k_reduce<<<KK, 128>>>((const float4*)encodings, (const float4*)embed_avg,
                          (float4*)out_ea, (float4*)out_norm);
}

// round 9
// speedup vs baseline: 1.1467x; 1.0719x over previous
#include <cuda_runtime.h>
#include <cuda_bf16.h>

// Problem constants (match reference_code)
#define NN 262144
#define KK 1024
#define DD 256
#define NBLK 128              // fused-prologue CTAs (all co-resident)
#define CHUNK 2048            // indices per CTA (NN / NBLK)
#define DECAY 0.99f
#define ONE_MINUS_DECAY 0.01f
#define EPS 1e-5f

// Scratch (device globals; no allocation allowed)
__device__ int      g_bh[NBLK * KK];     // [b][k] hist -> exclusive prefix over b
__device__ int      g_ktotal[KK];        // per-code total count
__device__ int      g_offsets[KK + 1];   // exclusive scan over codes
__device__ int      g_order[NN];         // row ids grouped by code
__device__ float    g_inv_smoothed[KK];
__device__ unsigned g_bar_cnt[4];        // software grid barrier state
__device__ unsigned g_bar_gen[4];        // (zero-init; replay-safe: gen monotone)

// ---------------------------------------------------------------------------
// Software grid barrier (all NBLK CTAs co-resident by construction).
// ---------------------------------------------------------------------------
__device__ __forceinline__ void grid_barrier(int id) {
    __syncthreads();
    if (threadIdx.x == 0) {
        volatile unsigned* genp = &g_bar_gen[id];
        unsigned gen = *genp;
        __threadfence();
        unsigned arrived = atomicAdd(&g_bar_cnt[id], 1u);
        if (arrived == (unsigned)(NBLK - 1)) {
            g_bar_cnt[id] = 0u;
            __threadfence();
            *genp = gen + 1u;
        } else {
            while (*genp == gen) { __nanosleep(64); }
        }
        __threadfence();
    }
    __syncthreads();
}

// ---------------------------------------------------------------------------
// Fused prologue: hist -> transpose scan -> code scan/cs epilogue -> scatter.
// Phase B now uses ALL 128 CTAs (8 codes each) to cut its latency 4x.
// Ends with PDL trigger so the reduce can overlap the launch boundary.
// ---------------------------------------------------------------------------
__global__ void __launch_bounds__(1024) k_prologue(
    const int* __restrict__ idx,
    const float* __restrict__ cluster_size,
    float* __restrict__ out_cs) {
    __shared__ union {
        int h[KK];            // phase A: histogram / phase D: cursors
        int s[NBLK][9];       // phase B: transpose-scan tile (8 codes + pad)
        struct { int wsum[32]; float wred[32]; float n_sh; } cs;  // phase C
    } sm;

    int t = threadIdx.x;
    int b = blockIdx.x;
    int lane = t & 31, warp = t >> 5;

    // ---- Phase A: per-CTA histogram (indices -> registers) ----
    sm.h[t] = 0;
    __syncthreads();
    int base = b * CHUNK;
    int k0 = idx[base + t];
    int k1 = idx[base + 1024 + t];
    atomicAdd(&sm.h[k0], 1);
    atomicAdd(&sm.h[k1], 1);
    __syncthreads();
    g_bh[b * KK + t] = sm.h[t];               // contiguous 4KB per CTA

    grid_barrier(0);

    // ---- Phase B: ALL 128 CTAs transpose-scan; CTA b owns codes b*8..b*8+7 ----
    {
        int c0 = b * 8;
        int row = t >> 3;        // 0..127
        int c   = t & 7;         // 0..7
        sm.s[row][c] = g_bh[row * KK + c0 + c];
        __syncthreads();
        if (warp < 8) {          // warp w scans code c0+w along the 128 blocks
            int w = warp;
            int carry = 0;
            #pragma unroll
            for (int seg = 0; seg < 4; ++seg) {
                int v = sm.s[seg * 32 + lane][w];
                int incl = v;
                #pragma unroll
                for (int o = 1; o < 32; o <<= 1) {
                    int x = __shfl_up_sync(0xffffffffu, incl, o);
                    if (lane >= o) incl += x;
                }
                sm.s[seg * 32 + lane][w] = carry + incl - v;   // exclusive
                carry += __shfl_sync(0xffffffffu, incl, 31);
            }
            if (lane == 0) g_ktotal[c0 + w] = carry;
        }
        __syncthreads();
        g_bh[row * KK + c0 + c] = sm.s[row][c];
    }

    grid_barrier(1);

    // ---- Phase C: CTA 32 scans code totals + cs epilogue ----
    if (b == 32) {
        int c = g_ktotal[t];
        int incl = c;
        #pragma unroll
        for (int o = 1; o < 32; o <<= 1) {
            int x = __shfl_up_sync(0xffffffffu, incl, o);
            if (lane >= o) incl += x;
        }
        if (lane == 31) sm.cs.wsum[warp] = incl;
        __syncthreads();
        if (warp == 0) {
            int s = sm.cs.wsum[lane];
            int si = s;
            #pragma unroll
            for (int o = 1; o < 32; o <<= 1) {
                int x = __shfl_up_sync(0xffffffffu, si, o);
                if (lane >= o) si += x;
            }
            sm.cs.wsum[lane] = si - s;
        }
        __syncthreads();
        int excl = incl - c + sm.cs.wsum[warp];

        g_offsets[t] = excl;
        if (t == KK - 1) g_offsets[KK] = excl + c;

        float ncs = cluster_size[t] * DECAY + ONE_MINUS_DECAY * (float)c;
        out_cs[t] = ncs;

        float v = ncs;
        #pragma unroll
        for (int o = 16; o > 0; o >>= 1)
            v += __shfl_down_sync(0xffffffffu, v, o);
        if (lane == 0) sm.cs.wred[warp] = v;
        __syncthreads();
        if (warp == 0) {
            float s = sm.cs.wred[lane];
            #pragma unroll
            for (int o = 16; o > 0; o >>= 1)
                s += __shfl_down_sync(0xffffffffu, s, o);
            if (lane == 0) sm.cs.n_sh = s;
        }
        __syncthreads();
        float n = sm.cs.n_sh;

        float smoothed = (ncs + EPS) / (n + (float)KK * EPS) * n;
        g_inv_smoothed[t] = 1.0f / smoothed;
    }

    grid_barrier(2);

    // ---- Phase D: scatter with register-held indices ----
    sm.h[t] = g_offsets[t] + g_bh[b * KK + t];   // coalesced, L2-hot
    __syncthreads();
    int p0 = atomicAdd(&sm.h[k0], 1);
    g_order[p0] = base + t;
    int p1 = atomicAdd(&sm.h[k1], 1);
    g_order[p1] = base + 1024 + t;

    // PDL: signal the dependent reduce that this CTA's writes are done.
    cudaTriggerProgrammaticLaunchCompletion();
}

// ---------------------------------------------------------------------------
// Reduce: per-code gather-reduce + fused EMA epilogue.
// 128 threads (64 float4 lanes x 2 row-phases), 1024 CTAs single wave,
// 8 independent streaming (__ldcs) float4 loads per thread.
// Launched with PDL: prefetches embed_avg, then waits on the prologue.
// ---------------------------------------------------------------------------
__global__ void __launch_bounds__(128) k_reduce(
    const float4* __restrict__ enc,        // [N, 64] float4
    const float4* __restrict__ embed_avg,  // [K, 64] float4
    float4* __restrict__ out_ea,
    float4* __restrict__ out_norm) {
    __shared__ int ord[1024];
    __shared__ float4 sh[64];

    int k = blockIdx.x;
    int d4 = threadIdx.x & 63;      // float4 column 0..63
    int ph = threadIdx.x >> 6;      // row phase 0..1
    size_t o = (size_t)k * 64 + d4;

    // Prologue-independent prefetch (embed_avg is a pure input).
    float4 ea = make_float4(0.f, 0.f, 0.f, 0.f);
    if (ph == 0) ea = embed_avg[o];

    // Wait for the prologue grid (PDL).
    cudaGridDependencySynchronize();

    int start = g_offsets[k];
    int cnt   = g_offsets[k + 1] - start;

    float4 a0 = make_float4(0.f, 0.f, 0.f, 0.f);
    float4 a1 = make_float4(0.f, 0.f, 0.f, 0.f);
    float4 a2 = make_float4(0.f, 0.f, 0.f, 0.f);
    float4 a3 = make_float4(0.f, 0.f, 0.f, 0.f);
    float4 a4 = make_float4(0.f, 0.f, 0.f, 0.f);
    float4 a5 = make_float4(0.f, 0.f, 0.f, 0.f);
    float4 a6 = make_float4(0.f, 0.f, 0.f, 0.f);
    float4 a7 = make_float4(0.f, 0.f, 0.f, 0.f);

    for (int t0 = 0; t0 < cnt; t0 += 1024) {
        int tile = min(1024, cnt - t0);
        __syncthreads();
        for (int i = threadIdx.x; i < tile; i += 128)
            ord[i] = g_order[start + t0 + i];
        __syncthreads();

        int j = ph;
        // 8 independent float4 streaming loads in flight per thread
        for (; j + 14 < tile; j += 16) {
            int r0 = ord[j];
            int r1 = ord[j + 2];
            int r2 = ord[j + 4];
            int r3 = ord[j + 6];
            int r4 = ord[j + 8];
            int r5 = ord[j + 10];
            int r6 = ord[j + 12];
            int r7 = ord[j + 14];
            float4 v0 = __ldcs(enc + (size_t)r0 * 64 + d4);
            float4 v1 = __ldcs(enc + (size_t)r1 * 64 + d4);
            float4 v2 = __ldcs(enc + (size_t)r2 * 64 + d4);
            float4 v3 = __ldcs(enc + (size_t)r3 * 64 + d4);
            float4 v4 = __ldcs(enc + (size_t)r4 * 64 + d4);
            float4 v5 = __ldcs(enc + (size_t)r5 * 64 + d4);
            float4 v6 = __ldcs(enc + (size_t)r6 * 64 + d4);
            float4 v7 = __ldcs(enc + (size_t)r7 * 64 + d4);
            a0.x += v0.x; a0.y += v0.y; a0.z += v0.z; a0.w += v0.w;
            a1.x += v1.x; a1.y += v1.y; a1.z += v1.z; a1.w += v1.w;
            a2.x += v2.x; a2.y += v2.y; a2.z += v2.z; a2.w += v2.w;
            a3.x += v3.x; a3.y += v3.y; a3.z += v3.z; a3.w += v3.w;
            a4.x += v4.x; a4.y += v4.y; a4.z += v4.z; a4.w += v4.w;
            a5.x += v5.x; a5.y += v5.y; a5.z += v5.z; a5.w += v5.w;
            a6.x += v6.x; a6.y += v6.y; a6.z += v6.z; a6.w += v6.w;
            a7.x += v7.x; a7.y += v7.y; a7.z += v7.z; a7.w += v7.w;
        }
        for (; j < tile; j += 2) {
            int r = ord[j];
            float4 v = __ldcs(enc + (size_t)r * 64 + d4);
            a0.x += v.x; a0.y += v.y; a0.z += v.z; a0.w += v.w;
        }
    }

    a0.x = ((a0.x + a1.x) + (a2.x + a3.x)) + ((a4.x + a5.x) + (a6.x + a7.x));
    a0.y = ((a0.y + a1.y) + (a2.y + a3.y)) + ((a4.y + a5.y) + (a6.y + a7.y));
    a0.z = ((a0.z + a1.z) + (a2.z + a3.z)) + ((a4.z + a5.z) + (a6.z + a7.z));
    a0.w = ((a0.w + a1.w) + (a2.w + a3.w)) + ((a4.w + a5.w) + (a6.w + a7.w));

    __syncthreads();
    if (ph == 1) sh[d4] = a0;
    __syncthreads();

    if (ph == 0) {
        float4 s1 = sh[d4];
        float4 acc;
        acc.x = a0.x + s1.x;
        acc.y = a0.y + s1.y;
        acc.z = a0.z + s1.z;
        acc.w = a0.w + s1.w;

        float4 nea;
        nea.x = ea.x * DECAY + ONE_MINUS_DECAY * acc.x;
        nea.y = ea.y * DECAY + ONE_MINUS_DECAY * acc.y;
        nea.z = ea.z * DECAY + ONE_MINUS_DECAY * acc.z;
        nea.w = ea.w * DECAY + ONE_MINUS_DECAY * acc.w;
        out_ea[o] = nea;
        float inv = g_inv_smoothed[k];
        float4 nrm;
        nrm.x = nea.x * inv; nrm.y = nea.y * inv;
        nrm.z = nea.z * inv; nrm.w = nea.w * inv;
        out_norm[o] = nrm;
    }
}

// ---------------------------------------------------------------------------
// Launch
// Inputs (metadata order): indices[int32 N], encodings[f32 N*D],
//                          cluster_size[f32 K], embed_avg[f32 K*D]
// Output: concat(new_cs[K], new_ea[K*D], embed_normalized[K*D])
// ---------------------------------------------------------------------------
extern "C" void kernel_launch(void* const* d_in, const int* in_sizes, int n_in,
                              void* d_out, int out_size) {
    const int*   indices      = (const int*)d_in[0];
    const float* encodings    = (const float*)d_in[1];
    const float* cluster_size = (const float*)d_in[2];
    const float* embed_avg    = (const float*)d_in[3];

    float* out_cs   = (float*)d_out;                 // [K]
    float* out_ea   = out_cs + KK;                   // [K, D]
    float* out_norm = out_ea + (size_t)KK * DD;      // [K, D]

    k_prologue<<<NBLK, 1024>>>(indices, cluster_size, out_cs);

    // PDL launch: reduce may start early, blocks in cudaGridDependencySynchronize
    cudaLaunchConfig_t cfg = {};
    cfg.gridDim = dim3(KK, 1, 1);
    cfg.blockDim = dim3(128, 1, 1);
    cfg.dynamicSmemBytes = 0;
    cfg.stream = 0;
    cudaLaunchAttribute attrs[1];
    attrs[0].id = cudaLaunchAttributeProgrammaticStreamSerialization;
    attrs[0].val.programmaticStreamSerializationAllowed = 1;
    cfg.attrs = attrs;
    cfg.numAttrs = 1;
    cudaLaunchKernelEx(&cfg, k_reduce,
                       (const float4*)encodings, (const float4*)embed_avg,
                       (float4*)out_ea, (float4*)out_norm);
}

// round 10
// speedup vs baseline: 1.1550x; 1.0072x over previous
#include <cuda_runtime.h>
#include <cuda_bf16.h>

// Problem constants (match reference_code)
#define NN 262144
#define KK 1024
#define DD 256
#define NBLK 128              // fused-prologue CTAs (all co-resident)
#define CHUNK 2048            // indices per CTA (NN / NBLK)
#define DECAY 0.99f
#define ONE_MINUS_DECAY 0.01f
#define EPS 1e-5f

// Scratch (device globals; no allocation allowed)
__device__ int      g_bh[NBLK * KK];     // [b][k] hist -> exclusive prefix over b
__device__ int      g_ktotal[KK];        // per-code total count
__device__ int      g_offsets[KK + 1];   // exclusive scan over codes
__device__ int      g_order[NN];         // row ids grouped by code
__device__ float    g_inv_smoothed[KK];
__device__ unsigned g_bar_cnt[4];        // software grid barrier state
__device__ unsigned g_bar_gen[4];        // (zero-init; replay-safe: gen monotone)

// ---------------------------------------------------------------------------
// Software grid barrier (all NBLK CTAs co-resident by construction).
// ---------------------------------------------------------------------------
__device__ __forceinline__ void grid_barrier(int id) {
    __syncthreads();
    if (threadIdx.x == 0) {
        volatile unsigned* genp = &g_bar_gen[id];
        unsigned gen = *genp;
        __threadfence();
        unsigned arrived = atomicAdd(&g_bar_cnt[id], 1u);
        if (arrived == (unsigned)(NBLK - 1)) {
            g_bar_cnt[id] = 0u;
            __threadfence();
            *genp = gen + 1u;
        } else {
            while (*genp == gen) { __nanosleep(64); }
        }
        __threadfence();
    }
    __syncthreads();
}

// ---------------------------------------------------------------------------
// Fused prologue: hist -> transpose scan -> (replicated) code scan -> scatter.
// Only TWO grid barriers: A->B and B->{C,D}. Phase C's integer scan is
// replicated in every CTA (cheap), removing the third barrier. CTA 32 alone
// writes the cs/inv_smoothed outputs. Ends with PDL trigger.
// ---------------------------------------------------------------------------
__global__ void __launch_bounds__(1024) k_prologue(
    const int* __restrict__ idx,
    const float* __restrict__ cluster_size,
    float* __restrict__ out_cs) {
    __shared__ union {
        int h[KK];            // phase A: histogram / phase D: cursors
        int s[NBLK][9];       // phase B: transpose-scan tile (8 codes + pad)
    } sm;
    __shared__ int   sh_wsum[32];     // phase C scan partials (disjoint from sm)
    __shared__ float sh_wred[32];
    __shared__ float sh_n;

    int t = threadIdx.x;
    int b = blockIdx.x;
    int lane = t & 31, warp = t >> 5;

    // ---- Phase A: per-CTA histogram (indices -> registers) ----
    sm.h[t] = 0;
    __syncthreads();
    int base = b * CHUNK;
    int k0 = idx[base + t];
    int k1 = idx[base + 1024 + t];
    atomicAdd(&sm.h[k0], 1);
    atomicAdd(&sm.h[k1], 1);
    __syncthreads();
    g_bh[b * KK + t] = sm.h[t];               // contiguous 4KB per CTA

    grid_barrier(0);

    // ---- Phase B: ALL 128 CTAs transpose-scan; CTA b owns codes b*8..b*8+7 ----
    {
        int c0 = b * 8;
        int row = t >> 3;        // 0..127
        int c   = t & 7;         // 0..7
        sm.s[row][c] = g_bh[row * KK + c0 + c];
        __syncthreads();
        if (warp < 8) {          // warp w scans code c0+w along the 128 blocks
            int w = warp;
            int carry = 0;
            #pragma unroll
            for (int seg = 0; seg < 4; ++seg) {
                int v = sm.s[seg * 32 + lane][w];
                int incl = v;
                #pragma unroll
                for (int o = 1; o < 32; o <<= 1) {
                    int x = __shfl_up_sync(0xffffffffu, incl, o);
                    if (lane >= o) incl += x;
                }
                sm.s[seg * 32 + lane][w] = carry + incl - v;   // exclusive
                carry += __shfl_sync(0xffffffffu, incl, 31);
            }
            if (lane == 0) g_ktotal[c0 + w] = carry;
        }
        __syncthreads();
        g_bh[row * KK + c0 + c] = sm.s[row][c];
    }

    grid_barrier(1);

    // ---- Phase C (replicated in every CTA): scan code totals -> excl offset ----
    int c = g_ktotal[t];
    int incl = c;
    #pragma unroll
    for (int o = 1; o < 32; o <<= 1) {
        int x = __shfl_up_sync(0xffffffffu, incl, o);
        if (lane >= o) incl += x;
    }
    if (lane == 31) sh_wsum[warp] = incl;
    __syncthreads();
    if (warp == 0) {
        int s = sh_wsum[lane];
        int si = s;
        #pragma unroll
        for (int o = 1; o < 32; o <<= 1) {
            int x = __shfl_up_sync(0xffffffffu, si, o);
            if (lane >= o) si += x;
        }
        sh_wsum[lane] = si - s;
    }
    __syncthreads();
    int excl = incl - c + sh_wsum[warp];

    if (b == 32) {
        // Outputs needed by the reduce kernel / harness (one CTA writes).
        g_offsets[t] = excl;
        if (t == KK - 1) g_offsets[KK] = excl + c;

        float ncs = cluster_size[t] * DECAY + ONE_MINUS_DECAY * (float)c;
        out_cs[t] = ncs;

        float v = ncs;
        #pragma unroll
        for (int o = 16; o > 0; o >>= 1)
            v += __shfl_down_sync(0xffffffffu, v, o);
        if (lane == 0) sh_wred[warp] = v;
        __syncthreads();
        if (warp == 0) {
            float s = sh_wred[lane];
            #pragma unroll
            for (int o = 16; o > 0; o >>= 1)
                s += __shfl_down_sync(0xffffffffu, s, o);
            if (lane == 0) sh_n = s;
        }
        __syncthreads();
        float n = sh_n;

        float smoothed = (ncs + EPS) / (n + (float)KK * EPS) * n;
        g_inv_smoothed[t] = 1.0f / smoothed;
    }

    // ---- Phase D: scatter, cursors built locally (no third barrier) ----
    int cursor = excl + g_bh[b * KK + t];     // local offsets + own block prefix
    __syncthreads();                          // sm.h reuse after phase B/C reads
    sm.h[t] = cursor;
    __syncthreads();
    int p0 = atomicAdd(&sm.h[k0], 1);
    g_order[p0] = base + t;
    int p1 = atomicAdd(&sm.h[k1], 1);
    g_order[p1] = base + 1024 + t;

    // PDL: signal the dependent reduce that this CTA's writes are done.
    cudaTriggerProgrammaticLaunchCompletion();
}

// ---------------------------------------------------------------------------
// Reduce: per-code gather-reduce + fused EMA epilogue. (unchanged — at the
// DRAM-efficiency roof for a 1KB-granularity permutation gather)
// ---------------------------------------------------------------------------
__global__ void __launch_bounds__(128) k_reduce(
    const float4* __restrict__ enc,        // [N, 64] float4
    const float4* __restrict__ embed_avg,  // [K, 64] float4
    float4* __restrict__ out_ea,
    float4* __restrict__ out_norm) {
    __shared__ int ord[1024];
    __shared__ float4 sh[64];

    int k = blockIdx.x;
    int d4 = threadIdx.x & 63;      // float4 column 0..63
    int ph = threadIdx.x >> 6;      // row phase 0..1
    size_t o = (size_t)k * 64 + d4;

    // Prologue-independent prefetch (embed_avg is a pure input).
    float4 ea = make_float4(0.f, 0.f, 0.f, 0.f);
    if (ph == 0) ea = embed_avg[o];

    // Wait for the prologue grid (PDL).
    cudaGridDependencySynchronize();

    int start = g_offsets[k];
    int cnt   = g_offsets[k + 1] - start;

    float4 a0 = make_float4(0.f, 0.f, 0.f, 0.f);
    float4 a1 = make_float4(0.f, 0.f, 0.f, 0.f);
    float4 a2 = make_float4(0.f, 0.f, 0.f, 0.f);
    float4 a3 = make_float4(0.f, 0.f, 0.f, 0.f);
    float4 a4 = make_float4(0.f, 0.f, 0.f, 0.f);
    float4 a5 = make_float4(0.f, 0.f, 0.f, 0.f);
    float4 a6 = make_float4(0.f, 0.f, 0.f, 0.f);
    float4 a7 = make_float4(0.f, 0.f, 0.f, 0.f);

    for (int t0 = 0; t0 < cnt; t0 += 1024) {
        int tile = min(1024, cnt - t0);
        __syncthreads();
        for (int i = threadIdx.x; i < tile; i += 128)
            ord[i] = g_order[start + t0 + i];
        __syncthreads();

        int j = ph;
        // 8 independent float4 streaming loads in flight per thread
        for (; j + 14 < tile; j += 16) {
            int r0 = ord[j];
            int r1 = ord[j + 2];
            int r2 = ord[j + 4];
            int r3 = ord[j + 6];
            int r4 = ord[j + 8];
            int r5 = ord[j + 10];
            int r6 = ord[j + 12];
            int r7 = ord[j + 14];
            float4 v0 = __ldcs(enc + (size_t)r0 * 64 + d4);
            float4 v1 = __ldcs(enc + (size_t)r1 * 64 + d4);
            float4 v2 = __ldcs(enc + (size_t)r2 * 64 + d4);
            float4 v3 = __ldcs(enc + (size_t)r3 * 64 + d4);
            float4 v4 = __ldcs(enc + (size_t)r4 * 64 + d4);
            float4 v5 = __ldcs(enc + (size_t)r5 * 64 + d4);
            float4 v6 = __ldcs(enc + (size_t)r6 * 64 + d4);
            float4 v7 = __ldcs(enc + (size_t)r7 * 64 + d4);
            a0.x += v0.x; a0.y += v0.y; a0.z += v0.z; a0.w += v0.w;
            a1.x += v1.x; a1.y += v1.y; a1.z += v1.z; a1.w += v1.w;
            a2.x += v2.x; a2.y += v2.y; a2.z += v2.z; a2.w += v2.w;
            a3.x += v3.x; a3.y += v3.y; a3.z += v3.z; a3.w += v3.w;
            a4.x += v4.x; a4.y += v4.y; a4.z += v4.z; a4.w += v4.w;
            a5.x += v5.x; a5.y += v5.y; a5.z += v5.z; a5.w += v5.w;
            a6.x += v6.x; a6.y += v6.y; a6.z += v6.z; a6.w += v6.w;
            a7.x += v7.x; a7.y += v7.y; a7.z += v7.z; a7.w += v7.w;
        }
        for (; j < tile; j += 2) {
            int r = ord[j];
            float4 v = __ldcs(enc + (size_t)r * 64 + d4);
            a0.x += v.x; a0.y += v.y; a0.z += v.z; a0.w += v.w;
        }
    }

    a0.x = ((a0.x + a1.x) + (a2.x + a3.x)) + ((a4.x + a5.x) + (a6.x + a7.x));
    a0.y = ((a0.y + a1.y) + (a2.y + a3.y)) + ((a4.y + a5.y) + (a6.y + a7.y));
    a0.z = ((a0.z + a1.z) + (a2.z + a3.z)) + ((a4.z + a5.z) + (a6.z + a7.z));
    a0.w = ((a0.w + a1.w) + (a2.w + a3.w)) + ((a4.w + a5.w) + (a6.w + a7.w));

    __syncthreads();
    if (ph == 1) sh[d4] = a0;
    __syncthreads();

    if (ph == 0) {
        float4 s1 = sh[d4];
        float4 acc;
        acc.x = a0.x + s1.x;
        acc.y = a0.y + s1.y;
        acc.z = a0.z + s1.z;
        acc.w = a0.w + s1.w;

        float4 nea;
        nea.x = ea.x * DECAY + ONE_MINUS_DECAY * acc.x;
        nea.y = ea.y * DECAY + ONE_MINUS_DECAY * acc.y;
        nea.z = ea.z * DECAY + ONE_MINUS_DECAY * acc.z;
        nea.w = ea.w * DECAY + ONE_MINUS_DECAY * acc.w;
        out_ea[o] = nea;
        float inv = g_inv_smoothed[k];
        float4 nrm;
        nrm.x = nea.x * inv; nrm.y = nea.y * inv;
        nrm.z = nea.z * inv; nrm.w = nea.w * inv;
        out_norm[o] = nrm;
    }
}

// ---------------------------------------------------------------------------
// Launch
// Inputs (metadata order): indices[int32 N], encodings[f32 N*D],
//                          cluster_size[f32 K], embed_avg[f32 K*D]
// Output: concat(new_cs[K], new_ea[K*D], embed_normalized[K*D])
// ---------------------------------------------------------------------------
extern "C" void kernel_launch(void* const* d_in, const int* in_sizes, int n_in,
                              void* d_out, int out_size) {
    const int*   indices      = (const int*)d_in[0];
    const float* encodings    = (const float*)d_in[1];
    const float* cluster_size = (const float*)d_in[2];
    const float* embed_avg    = (const float*)d_in[3];

    float* out_cs   = (float*)d_out;                 // [K]
    float* out_ea   = out_cs + KK;                   // [K, D]
    float* out_norm = out_ea + (size_t)KK * DD;      // [K, D]

    k_prologue<<<NBLK, 1024>>>(indices, cluster_size, out_cs);

    // PDL launch: reduce may start early, blocks in cudaGridDependencySynchronize
    cudaLaunchConfig_t cfg = {};
    cfg.gridDim = dim3(KK, 1, 1);
    cfg.blockDim = dim3(128, 1, 1);
    cfg.dynamicSmemBytes = 0;
    cfg.stream = 0;
    cudaLaunchAttribute attrs[1];
    attrs[0].id = cudaLaunchAttributeProgrammaticStreamSerialization;
    attrs[0].val.programmaticStreamSerializationAllowed = 1;
    cfg.attrs = attrs;
    cfg.numAttrs = 1;
    cudaLaunchKernelEx(&cfg, k_reduce,
                       (const float4*)encodings, (const float4*)embed_avg,
                       (float4*)out_ea, (float4*)out_norm);
}